// round 2
// baseline (speedup 1.0000x reference)
#include <cuda_runtime.h>
#include <math.h>

#define D 64
#define NMAX 100000
#define EMAX 1600000

// Scratch (__device__ globals, allocation-free rule)
__device__ float g_xw[3ULL * NMAX * D];    // [0]=x@W_low [1]=x@W_high [2]=x@W_mlp
__device__ float g_acc[2ULL * NMAX * D];   // [0]=acc_low [1]=acc_high (pre-relu)
__device__ int   g_deg[NMAX];
__device__ int   g_rowstart[NMAX];
__device__ int   g_cursor[NMAX];
__device__ int   g_csrc[EMAX];             // src | (k<<20), k in {0,1,2}
__device__ float g_cvl[EMAX];
__device__ float g_cvh[EMAX];

// ---------------- CSR build ----------------

__global__ void zero_deg_kernel(int n) {
    int i = blockIdx.x * blockDim.x + threadIdx.x;
    if (i < n) g_deg[i] = 0;
}

__global__ void hist_kernel(const int* __restrict__ dst, int e) {
    int i = blockIdx.x * blockDim.x + threadIdx.x;
    if (i < e) atomicAdd(&g_deg[dst[i]], 1);
}

// One-block exclusive scan over g_deg -> g_rowstart, g_cursor.
__global__ void scan_kernel(int n) {
    __shared__ int ssum[1024];
    int t = threadIdx.x;
    int chunk = (n + 1023) >> 10;
    int lo = t * chunk;
    int hi = min(lo + chunk, n);
    int s = 0;
    for (int i = lo; i < hi; i++) s += g_deg[i];
    ssum[t] = s;
    __syncthreads();
    // inclusive Hillis-Steele scan
    for (int d = 1; d < 1024; d <<= 1) {
        int v = (t >= d) ? ssum[t - d] : 0;
        __syncthreads();
        ssum[t] += v;
        __syncthreads();
    }
    int off = ssum[t] - s;  // exclusive prefix of this chunk
    for (int i = lo; i < hi; i++) {
        g_rowstart[i] = off;
        g_cursor[i] = off;
        off += g_deg[i];
    }
}

__global__ void scatter_kernel(const int* __restrict__ src,
                               const int* __restrict__ dst,
                               const int* __restrict__ lab,
                               const float* __restrict__ vl,
                               const float* __restrict__ vh,
                               int e) {
    int i = blockIdx.x * blockDim.x + threadIdx.x;
    if (i >= e) return;
    int s = src[i], d = dst[i];
    int sl = lab[s], dl = lab[d];
    int k = ((sl < 0) || (dl < 0)) ? 2 : ((sl != dl) ? 1 : 0);
    int pos = atomicAdd(&g_cursor[d], 1);
    g_csrc[pos] = s | (k << 20);
    g_cvl[pos] = vl[i];
    g_cvh[pos] = vh[i];
}

// ---------------- dense 3-way GEMM ----------------

__global__ void gemm3_kernel(const float* __restrict__ x,
                             const float* __restrict__ wl,
                             const float* __restrict__ wh,
                             const float* __restrict__ wm,
                             int n) {
    __shared__ float sW[3][D][D];
    for (int i = threadIdx.x; i < D * D; i += blockDim.x) {
        sW[0][i >> 6][i & 63] = wl[i];
        sW[1][i >> 6][i & 63] = wh[i];
        sW[2][i >> 6][i & 63] = wm[i];
    }
    __syncthreads();
    int warp = threadIdx.x >> 5, lane = threadIdx.x & 31;
    int row = blockIdx.x * 8 + warp;
    if (row >= n) return;
    float2 xv = *(const float2*)(x + (size_t)row * D + lane * 2);
    float a0 = 0.f, a1 = 0.f, b0 = 0.f, b1 = 0.f, c0 = 0.f, c1 = 0.f;
#pragma unroll
    for (int k = 0; k < D; k++) {
        float xk = __shfl_sync(0xffffffffu, (k & 1) ? xv.y : xv.x, k >> 1);
        a0 += xk * sW[0][k][lane];      a1 += xk * sW[0][k][lane + 32];
        b0 += xk * sW[1][k][lane];      b1 += xk * sW[1][k][lane + 32];
        c0 += xk * sW[2][k][lane];      c1 += xk * sW[2][k][lane + 32];
    }
    size_t nd = (size_t)n * D;
    size_t o = (size_t)row * D;
    g_xw[o + lane] = a0;               g_xw[o + lane + 32] = a1;
    g_xw[nd + o + lane] = b0;          g_xw[nd + o + lane + 32] = b1;
    g_xw[2 * nd + o + lane] = c0;      g_xw[2 * nd + o + lane + 32] = c1;
}

// ---------------- dst-centric SpMM (warp per node, no atomics) ----------------

__global__ void spmm_csr_kernel(int n) {
    int warp = threadIdx.x >> 5, lane = threadIdx.x & 31;
    int node = blockIdx.x * 8 + warp;
    if (node >= n) return;
    int start = g_rowstart[node];
    int deg = g_deg[node];
    size_t nd = (size_t)n * D;
    const float2* xl = (const float2*)g_xw;
    const float2* xh = (const float2*)(g_xw + nd);
    float2 al = make_float2(0.f, 0.f), ah = make_float2(0.f, 0.f);
#pragma unroll 4
    for (int i = 0; i < deg; i++) {
        int s = g_csrc[start + i] & 0xFFFFF;
        float a = g_cvl[start + i];
        float b = g_cvh[start + i];
        float2 fl = xl[(size_t)s * 32 + lane];
        float2 fh = xh[(size_t)s * 32 + lane];
        al.x += a * fl.x; al.y += a * fl.y;
        ah.x += b * fh.x; ah.y += b * fh.y;
    }
    ((float2*)g_acc)[(size_t)node * 32 + lane] = al;
    ((float2*)(g_acc + nd))[(size_t)node * 32 + lane] = ah;
}

// ---------------- fused bucket-agg + attention epilogue (warp per node) ----------------

__global__ void agg_final_kernel(const float* __restrict__ alf, const float* __restrict__ ahf,
                                 const float* __restrict__ alb, const float* __restrict__ ahb,
                                 const float* __restrict__ alu, const float* __restrict__ ahu,
                                 const float* __restrict__ am,  const float* __restrict__ a7,
                                 float* __restrict__ out, int n) {
    __shared__ float sAtt[7][D];
    __shared__ float sA7[49];
    if (threadIdx.x < D) {
        int c = threadIdx.x;
        sAtt[0][c] = alf[c]; sAtt[1][c] = ahf[c]; sAtt[2][c] = alb[c];
        sAtt[3][c] = ahb[c]; sAtt[4][c] = alu[c]; sAtt[5][c] = ahu[c];
        sAtt[6][c] = am[c];
    }
    if (threadIdx.x < 49) sA7[threadIdx.x] = a7[threadIdx.x];
    __syncthreads();
    int warp = threadIdx.x >> 5, lane = threadIdx.x & 31;
    int node = blockIdx.x * 8 + warp;
    if (node >= n) return;
    int start = g_rowstart[node];
    int deg = g_deg[node];
    size_t nd = (size_t)n * D;
    const float2* xl = (const float2*)g_acc;
    const float2* xh = (const float2*)(g_acc + nd);

    // buckets: 0=homo 1=hete 2=unk, low then high
    float2 b0l = make_float2(0.f, 0.f), b1l = b0l, b2l = b0l;
    float2 b0h = b0l, b1h = b0l, b2h = b0l;
#pragma unroll 4
    for (int i = 0; i < deg; i++) {
        int sw = g_csrc[start + i];
        int s = sw & 0xFFFFF;
        int k = sw >> 20;
        float2 fl = xl[(size_t)s * 32 + lane];
        float2 fh = xh[(size_t)s * 32 + lane];
        fl.x = fmaxf(fl.x, 0.f); fl.y = fmaxf(fl.y, 0.f);
        fh.x = fmaxf(fh.x, 0.f); fh.y = fmaxf(fh.y, 0.f);
        float m0 = (k == 0) ? 1.f : 0.f;
        float m1 = (k == 1) ? 1.f : 0.f;
        float m2 = (k == 2) ? 1.f : 0.f;
        b0l.x += m0 * fl.x; b0l.y += m0 * fl.y;
        b1l.x += m1 * fl.x; b1l.y += m1 * fl.y;
        b2l.x += m2 * fl.x; b2l.y += m2 * fl.y;
        b0h.x += m0 * fh.x; b0h.y += m0 * fh.y;
        b1h.x += m1 * fh.x; b1h.y += m1 * fh.y;
        b2h.x += m2 * fh.x; b2h.y += m2 * fh.y;
    }

    size_t o = (size_t)node * D + lane * 2;
    float2 ml = *(const float2*)(g_xw + 2 * nd + o);
    float2 mlp;
    mlp.x = fmaxf(ml.x, 0.f); mlp.y = fmaxf(ml.y, 0.f);

    int c = lane * 2;
    float pd[7];
    pd[0] = b1l.x * sAtt[0][c] + b1l.y * sAtt[0][c + 1];
    pd[1] = b1h.x * sAtt[1][c] + b1h.y * sAtt[1][c + 1];
    pd[2] = b0l.x * sAtt[2][c] + b0l.y * sAtt[2][c + 1];
    pd[3] = b0h.x * sAtt[3][c] + b0h.y * sAtt[3][c + 1];
    pd[4] = b2l.x * sAtt[4][c] + b2l.y * sAtt[4][c + 1];
    pd[5] = b2h.x * sAtt[5][c] + b2h.y * sAtt[5][c + 1];
    pd[6] = mlp.x * sAtt[6][c] + mlp.y * sAtt[6][c + 1];
#pragma unroll
    for (int off = 16; off; off >>= 1) {
#pragma unroll
        for (int j = 0; j < 7; j++)
            pd[j] += __shfl_xor_sync(0xffffffffu, pd[j], off);
    }
    float f[7];
#pragma unroll
    for (int j = 0; j < 7; j++)
        f[j] = 1.f / (1.f + expf(-pd[j]));
    float lg[7];
    float m = -1e30f;
#pragma unroll
    for (int i = 0; i < 7; i++) {
        float s = 0.f;
#pragma unroll
        for (int j = 0; j < 7; j++) s += f[j] * sA7[j * 7 + i];
        lg[i] = s * (1.0f / 7.0f);
        m = fmaxf(m, lg[i]);
    }
    float sum = 0.f;
#pragma unroll
    for (int i = 0; i < 7; i++) { lg[i] = expf(lg[i] - m); sum += lg[i]; }
    float inv = 7.0f / sum;
#pragma unroll
    for (int i = 0; i < 7; i++) lg[i] *= inv;

    float2 r;
    r.x = lg[0] * b1l.x + lg[1] * b1h.x + lg[2] * b0l.x + lg[3] * b0h.x
        + lg[4] * b2l.x + lg[5] * b2h.x + lg[6] * mlp.x;
    r.y = lg[0] * b1l.y + lg[1] * b1h.y + lg[2] * b0l.y + lg[3] * b0h.y
        + lg[4] * b2l.y + lg[5] * b2h.y + lg[6] * mlp.y;
    *(float2*)(out + o) = r;
}

extern "C" void kernel_launch(void* const* d_in, const int* in_sizes, int n_in,
                              void* d_out, int out_size) {
    const float* x   = (const float*)d_in[0];
    const float* vl  = (const float*)d_in[1];
    const float* vh  = (const float*)d_in[2];
    const float* wl  = (const float*)d_in[3];
    const float* wh  = (const float*)d_in[4];
    const float* wm  = (const float*)d_in[5];
    const float* alf = (const float*)d_in[6];
    const float* ahf = (const float*)d_in[7];
    const float* alb = (const float*)d_in[8];
    const float* ahb = (const float*)d_in[9];
    const float* alu = (const float*)d_in[10];
    const float* ahu = (const float*)d_in[11];
    const float* am  = (const float*)d_in[12];
    const float* a7  = (const float*)d_in[13];
    const int* src   = (const int*)d_in[14];
    const int* dst   = (const int*)d_in[15];
    const int* lab   = (const int*)d_in[16];
    int n = in_sizes[0] / D;
    int e = in_sizes[14];
    float* out = (float*)d_out;

    zero_deg_kernel<<<(n + 255) / 256, 256>>>(n);
    hist_kernel<<<(e + 255) / 256, 256>>>(dst, e);
    scan_kernel<<<1, 1024>>>(n);
    scatter_kernel<<<(e + 255) / 256, 256>>>(src, dst, lab, vl, vh, e);
    gemm3_kernel<<<(n + 7) / 8, 256>>>(x, wl, wh, wm, n);
    spmm_csr_kernel<<<(n + 7) / 8, 256>>>(n);
    agg_final_kernel<<<(n + 7) / 8, 256>>>(alf, ahf, alb, ahb, alu, ahu, am, a7, out, n);
}

// round 3
// speedup vs baseline: 1.1479x; 1.1479x over previous
#include <cuda_runtime.h>
#include <math.h>

#define D 64
#define NMAX 100000
#define EMAX 1600000

// Scratch (__device__ globals, allocation-free rule)
__device__ float g_xwlh[(size_t)NMAX * 128];  // [node][0:64]=x@W_low, [64:128]=x@W_high
__device__ float g_mlp[(size_t)NMAX * 64];    // relu(x@W_mlp)
__device__ float g_acc2[(size_t)NMAX * 128];  // interleaved acc low/high; relu'd in nodeA
__device__ float g_t[(size_t)NMAX * 8];       // per node: (tlow_k, thigh_k) pairs, k=0..2
__device__ float g_pd[(size_t)NMAX * 8];      // attention logits, slots 0..6
__device__ float g_w2[(size_t)NMAX * 8];      // per node: (wl_k, wh_k) pairs, k=0..2
__device__ int   g_ek[EMAX];                  // src | (k<<20)

__device__ __forceinline__ void red4(float* a, float x, float y, float z, float w) {
    asm volatile("red.global.add.v4.f32 [%0], {%1, %2, %3, %4};"
                 :: "l"(a), "f"(x), "f"(y), "f"(z), "f"(w) : "memory");
}
__device__ __forceinline__ void red2(float* a, float x, float y) {
    asm volatile("red.global.add.v2.f32 [%0], {%1, %2};"
                 :: "l"(a), "f"(x), "f"(y) : "memory");
}

__global__ void zero_kernel(int n) {
    int i = blockIdx.x * blockDim.x + threadIdx.x;
    int nacc = n * 32;             // float4s in g_acc2
    if (i < nacc) ((float4*)g_acc2)[i] = make_float4(0.f, 0.f, 0.f, 0.f);
    else if (i < nacc + n * 2) ((float4*)g_pd)[i - nacc] = make_float4(0.f, 0.f, 0.f, 0.f);
}

// 3 fused GEMMs: warp per row, weights staged in shared.
__global__ void gemm3_kernel(const float* __restrict__ x,
                             const float* __restrict__ wl,
                             const float* __restrict__ wh,
                             const float* __restrict__ wm,
                             int n) {
    __shared__ float sW[3][D][D];
    for (int i = threadIdx.x; i < D * D; i += blockDim.x) {
        sW[0][i >> 6][i & 63] = wl[i];
        sW[1][i >> 6][i & 63] = wh[i];
        sW[2][i >> 6][i & 63] = wm[i];
    }
    __syncthreads();
    int warp = threadIdx.x >> 5, lane = threadIdx.x & 31;
    int row = blockIdx.x * 8 + warp;
    if (row >= n) return;
    float2 xv = *(const float2*)(x + (size_t)row * D + lane * 2);
    float a0 = 0.f, a1 = 0.f, b0 = 0.f, b1 = 0.f, c0 = 0.f, c1 = 0.f;
#pragma unroll
    for (int k = 0; k < D; k++) {
        float xk = __shfl_sync(0xffffffffu, (k & 1) ? xv.y : xv.x, k >> 1);
        a0 += xk * sW[0][k][lane];      a1 += xk * sW[0][k][lane + 32];
        b0 += xk * sW[1][k][lane];      b1 += xk * sW[1][k][lane + 32];
        c0 += xk * sW[2][k][lane];      c1 += xk * sW[2][k][lane + 32];
    }
    size_t o = (size_t)row * 128;
    g_xwlh[o + lane] = a0;            g_xwlh[o + lane + 32] = a1;
    g_xwlh[o + 64 + lane] = b0;       g_xwlh[o + 96 + lane] = b1;
    size_t om = (size_t)row * 64;
    g_mlp[om + lane] = fmaxf(c0, 0.f);
    g_mlp[om + lane + 32] = fmaxf(c1, 0.f);
}

// pass1: edge-parallel SpMM, 16 threads/edge, red4 scatter into interleaved acc.
__global__ void spmm_kernel(const float* __restrict__ vl,
                            const float* __restrict__ vh,
                            const int* __restrict__ src,
                            const int* __restrict__ dst,
                            int e) {
    int tid = blockIdx.x * blockDim.x + threadIdx.x;
    int eid = tid >> 4;
    if (eid >= e) return;
    int c = (tid & 15) << 2;
    int s = src[eid], d = dst[eid];
    float a = vl[eid], b = vh[eid];
    const float4* ps = (const float4*)(g_xwlh + (size_t)s * 128);
    float4 fl = ps[c >> 2];
    float4 fh = ps[16 + (c >> 2)];
    float* pd = g_acc2 + (size_t)d * 128;
    red4(pd + c, a * fl.x, a * fl.y, a * fl.z, a * fl.w);
    red4(pd + 64 + c, b * fh.x, b * fh.y, b * fh.z, b * fh.w);
}

// nodeA: relu(acc) in place + 6 attention dot products + mlp logit. Warp per node.
__global__ void nodeA_kernel(const float* __restrict__ alf, const float* __restrict__ ahf,
                             const float* __restrict__ alb, const float* __restrict__ ahb,
                             const float* __restrict__ alu, const float* __restrict__ ahu,
                             const float* __restrict__ am, int n) {
    __shared__ float sAl[3][D];  // by bucket k: 0=homo(be) 1=hete(fr) 2=unk
    __shared__ float sAh[3][D];
    __shared__ float sAm[D];
    if (threadIdx.x < D) {
        int c = threadIdx.x;
        sAl[0][c] = alb[c]; sAl[1][c] = alf[c]; sAl[2][c] = alu[c];
        sAh[0][c] = ahb[c]; sAh[1][c] = ahf[c]; sAh[2][c] = ahu[c];
        sAm[c] = am[c];
    }
    __syncthreads();
    int warp = threadIdx.x >> 5, lane = threadIdx.x & 31;
    int node = blockIdx.x * 8 + warp;
    if (node >= n) return;
    int c = lane * 2;
    float2* pacc = (float2*)(g_acc2 + (size_t)node * 128);
    float2 l = pacc[lane];
    float2 h = pacc[32 + lane];
    l.x = fmaxf(l.x, 0.f); l.y = fmaxf(l.y, 0.f);
    h.x = fmaxf(h.x, 0.f); h.y = fmaxf(h.y, 0.f);
    pacc[lane] = l;
    pacc[32 + lane] = h;
    float2 m2 = ((const float2*)(g_mlp + (size_t)node * 64))[lane];
    float dv[7];
#pragma unroll
    for (int k = 0; k < 3; k++) {
        dv[2 * k]     = l.x * sAl[k][c] + l.y * sAl[k][c + 1];
        dv[2 * k + 1] = h.x * sAh[k][c] + h.y * sAh[k][c + 1];
    }
    dv[6] = m2.x * sAm[c] + m2.y * sAm[c + 1];
#pragma unroll
    for (int off = 16; off; off >>= 1)
#pragma unroll
        for (int j = 0; j < 7; j++)
            dv[j] += __shfl_xor_sync(0xffffffffu, dv[j], off);
    if (lane == 0) {
        float* pt = g_t + (size_t)node * 8;
        pt[0] = dv[0]; pt[1] = dv[1];   // k=0 (homo): low, high
        pt[2] = dv[2]; pt[3] = dv[3];   // k=1 (hete)
        pt[4] = dv[4]; pt[5] = dv[5];   // k=2 (unk)
        g_pd[(size_t)node * 8 + 6] = dv[6];
    }
}

// pass2: scatter per-edge logit contributions (one red2 per edge) + pack src|k.
__global__ void pass2_kernel(const int* __restrict__ src,
                             const int* __restrict__ dst,
                             const int* __restrict__ lab,
                             int e) {
    int i = blockIdx.x * blockDim.x + threadIdx.x;
    if (i >= e) return;
    int s = src[i], d = dst[i];
    int sl = lab[s], dl = lab[d];
    int k = ((sl | dl) < 0) ? 2 : ((sl != dl) ? 1 : 0);
    g_ek[i] = s | (k << 20);
    float2 t = *(const float2*)(g_t + (size_t)s * 8 + 2 * k);
    // pd slot pairs by bucket: k=0 -> (2,3), k=1 -> (0,1), k=2 -> (4,5)
    int slot = (k == 1) ? 0 : ((k == 0) ? 2 : 4);
    red2(g_pd + (size_t)d * 8 + slot, t.x, t.y);
}

// nodeB: attention softmax -> per-bucket weights + out init with mlp term. Warp per node.
__global__ void nodeB_kernel(const float* __restrict__ a7, float* __restrict__ out, int n) {
    __shared__ float sA7[49];
    if (threadIdx.x < 49) sA7[threadIdx.x] = a7[threadIdx.x];
    __syncthreads();
    int warp = threadIdx.x >> 5, lane = threadIdx.x & 31;
    int node = blockIdx.x * 8 + warp;
    if (node >= n) return;
    const float* pd = g_pd + (size_t)node * 8;
    float f[7];
#pragma unroll
    for (int j = 0; j < 7; j++)
        f[j] = 1.f / (1.f + expf(-pd[j]));
    float lg[7];
    float m = -1e30f;
#pragma unroll
    for (int i = 0; i < 7; i++) {
        float s = 0.f;
#pragma unroll
        for (int j = 0; j < 7; j++) s += f[j] * sA7[j * 7 + i];
        lg[i] = s * (1.0f / 7.0f);
        m = fmaxf(m, lg[i]);
    }
    float sum = 0.f;
#pragma unroll
    for (int i = 0; i < 7; i++) { lg[i] = expf(lg[i] - m); sum += lg[i]; }
    float inv = 7.0f / sum;
#pragma unroll
    for (int i = 0; i < 7; i++) lg[i] *= inv;

    if (lane < 3) {
        int k = lane;
        float wlk = (k == 1) ? lg[0] : ((k == 0) ? lg[2] : lg[4]);
        float whk = (k == 1) ? lg[1] : ((k == 0) ? lg[3] : lg[5]);
        ((float2*)(g_w2 + (size_t)node * 8))[k] = make_float2(wlk, whk);
    }
    float2 m2 = ((const float2*)(g_mlp + (size_t)node * 64))[lane];
    float2 r;
    r.x = lg[6] * m2.x;
    r.y = lg[6] * m2.y;
    ((float2*)(out + (size_t)node * 64))[lane] = r;
}

// pass3: weighted gather-scatter of relu'd acc into out. 16 threads/edge.
__global__ void pass3_kernel(const int* __restrict__ dst, float* __restrict__ out, int e) {
    int tid = blockIdx.x * blockDim.x + threadIdx.x;
    int eid = tid >> 4;
    if (eid >= e) return;
    int c4 = tid & 15;
    int ek = g_ek[eid];
    int s = ek & 0xFFFFF;
    int k = ek >> 20;
    int d = dst[eid];
    float2 w = *(const float2*)(g_w2 + (size_t)d * 8 + 2 * k);
    const float4* ps = (const float4*)(g_acc2 + (size_t)s * 128);
    float4 fl = ps[c4];
    float4 fh = ps[16 + c4];
    red4(out + (size_t)d * 64 + c4 * 4,
         w.x * fl.x + w.y * fh.x,
         w.x * fl.y + w.y * fh.y,
         w.x * fl.z + w.y * fh.z,
         w.x * fl.w + w.y * fh.w);
}

extern "C" void kernel_launch(void* const* d_in, const int* in_sizes, int n_in,
                              void* d_out, int out_size) {
    const float* x   = (const float*)d_in[0];
    const float* vl  = (const float*)d_in[1];
    const float* vh  = (const float*)d_in[2];
    const float* wl  = (const float*)d_in[3];
    const float* wh  = (const float*)d_in[4];
    const float* wm  = (const float*)d_in[5];
    const float* alf = (const float*)d_in[6];
    const float* ahf = (const float*)d_in[7];
    const float* alb = (const float*)d_in[8];
    const float* ahb = (const float*)d_in[9];
    const float* alu = (const float*)d_in[10];
    const float* ahu = (const float*)d_in[11];
    const float* am  = (const float*)d_in[12];
    const float* a7  = (const float*)d_in[13];
    const int* src   = (const int*)d_in[14];
    const int* dst   = (const int*)d_in[15];
    const int* lab   = (const int*)d_in[16];
    int n = in_sizes[0] / D;
    int e = in_sizes[14];
    float* out = (float*)d_out;

    int nz = n * 34;  // float4s: acc2 (32/node) + pd (2/node)
    zero_kernel<<<(nz + 255) / 256, 256>>>(n);
    gemm3_kernel<<<(n + 7) / 8, 256>>>(x, wl, wh, wm, n);
    int et = e * 16;
    spmm_kernel<<<(et + 255) / 256, 256>>>(vl, vh, src, dst, e);
    nodeA_kernel<<<(n + 7) / 8, 256>>>(alf, ahf, alb, ahb, alu, ahu, am, n);
    pass2_kernel<<<(e + 255) / 256, 256>>>(src, dst, lab, e);
    nodeB_kernel<<<(n + 7) / 8, 256>>>(a7, out, n);
    pass3_kernel<<<(et + 255) / 256, 256>>>(dst, out, e);
}

// round 4
// speedup vs baseline: 1.2015x; 1.0466x over previous
#include <cuda_runtime.h>
#include <cuda_fp16.h>
#include <math.h>

#define D 64
#define NMAX 100000
#define EMAX 1600000

// Scratch (__device__ globals, allocation-free rule)
__device__ __half2 g_xwp[(size_t)NMAX * 64];  // [node*64+c] = (xw_low[c], xw_high[c])
__device__ float   g_mlp[(size_t)NMAX * 64];  // relu(x@W_mlp)
__device__ float   g_acc2[(size_t)NMAX * 128];// [node][low 0:64 | high 64:128], fp32 atomics
__device__ __half2 g_rel[(size_t)NMAX * 64];  // relu'd acc, packed (low, high)
__device__ float   g_t[(size_t)NMAX * 8];     // per node: (tlow_k, thigh_k) pairs, k=0..2
__device__ float   g_pd[(size_t)NMAX * 8];    // attention logits, slots 0..6
__device__ float   g_w2[(size_t)NMAX * 8];    // per node: (wl_k, wh_k) pairs, k=0..2
__device__ int     g_ek[EMAX];                // src | (k<<20)

__device__ __forceinline__ void red4(float* a, float x, float y, float z, float w) {
    asm volatile("red.global.add.v4.f32 [%0], {%1, %2, %3, %4};"
                 :: "l"(a), "f"(x), "f"(y), "f"(z), "f"(w) : "memory");
}
__device__ __forceinline__ void red2(float* a, float x, float y) {
    asm volatile("red.global.add.v2.f32 [%0], {%1, %2};"
                 :: "l"(a), "f"(x), "f"(y) : "memory");
}

__global__ void zero_kernel(int n) {
    int i = blockIdx.x * blockDim.x + threadIdx.x;
    int nacc = n * 32;             // float4s in g_acc2
    if (i < nacc) ((float4*)g_acc2)[i] = make_float4(0.f, 0.f, 0.f, 0.f);
    else if (i < nacc + n * 2) ((float4*)g_pd)[i - nacc] = make_float4(0.f, 0.f, 0.f, 0.f);
}

// 3 fused GEMMs: warp per row, weights staged in shared. Low/high packed to half2.
__global__ void gemm3_kernel(const float* __restrict__ x,
                             const float* __restrict__ wl,
                             const float* __restrict__ wh,
                             const float* __restrict__ wm,
                             int n) {
    __shared__ float sW[3][D][D];
    for (int i = threadIdx.x; i < D * D; i += blockDim.x) {
        sW[0][i >> 6][i & 63] = wl[i];
        sW[1][i >> 6][i & 63] = wh[i];
        sW[2][i >> 6][i & 63] = wm[i];
    }
    __syncthreads();
    int warp = threadIdx.x >> 5, lane = threadIdx.x & 31;
    int row = blockIdx.x * 8 + warp;
    if (row >= n) return;
    float2 xv = *(const float2*)(x + (size_t)row * D + lane * 2);
    float a0 = 0.f, a1 = 0.f, b0 = 0.f, b1 = 0.f, c0 = 0.f, c1 = 0.f;
#pragma unroll
    for (int k = 0; k < D; k++) {
        float xk = __shfl_sync(0xffffffffu, (k & 1) ? xv.y : xv.x, k >> 1);
        a0 += xk * sW[0][k][lane];      a1 += xk * sW[0][k][lane + 32];
        b0 += xk * sW[1][k][lane];      b1 += xk * sW[1][k][lane + 32];
        c0 += xk * sW[2][k][lane];      c1 += xk * sW[2][k][lane + 32];
    }
    size_t o = (size_t)row * 64;
    g_xwp[o + lane]      = __floats2half2_rn(a0, b0);
    g_xwp[o + lane + 32] = __floats2half2_rn(a1, b1);
    g_mlp[o + lane] = fmaxf(c0, 0.f);
    g_mlp[o + lane + 32] = fmaxf(c1, 0.f);
}

// pass1: edge-parallel SpMM, 16 threads/edge. One float4 = 4 half2 (low,high) columns.
__global__ void spmm_kernel(const float* __restrict__ vl,
                            const float* __restrict__ vh,
                            const int* __restrict__ src,
                            const int* __restrict__ dst,
                            int e) {
    int tid = blockIdx.x * blockDim.x + threadIdx.x;
    int eid = tid >> 4;
    if (eid >= e) return;
    int c4 = tid & 15;
    int s = src[eid], d = dst[eid];
    float a = vl[eid], b = vh[eid];
    float4 raw = ((const float4*)(g_xwp + (size_t)s * 64))[c4];
    __half2 h0 = *(__half2*)&raw.x, h1 = *(__half2*)&raw.y;
    __half2 h2 = *(__half2*)&raw.z, h3 = *(__half2*)&raw.w;
    float2 f0 = __half22float2(h0), f1 = __half22float2(h1);
    float2 f2 = __half22float2(h2), f3 = __half22float2(h3);
    float* pd = g_acc2 + (size_t)d * 128 + c4 * 4;
    red4(pd,      a * f0.x, a * f1.x, a * f2.x, a * f3.x);
    red4(pd + 64, b * f0.y, b * f1.y, b * f2.y, b * f3.y);
}

// nodeA: relu(acc) -> packed half2 g_rel + 6 attention dot products + mlp logit.
__global__ void nodeA_kernel(const float* __restrict__ alf, const float* __restrict__ ahf,
                             const float* __restrict__ alb, const float* __restrict__ ahb,
                             const float* __restrict__ alu, const float* __restrict__ ahu,
                             const float* __restrict__ am, int n) {
    __shared__ float sAl[3][D];  // by bucket k: 0=homo(be) 1=hete(fr) 2=unk
    __shared__ float sAh[3][D];
    __shared__ float sAm[D];
    if (threadIdx.x < D) {
        int c = threadIdx.x;
        sAl[0][c] = alb[c]; sAl[1][c] = alf[c]; sAl[2][c] = alu[c];
        sAh[0][c] = ahb[c]; sAh[1][c] = ahf[c]; sAh[2][c] = ahu[c];
        sAm[c] = am[c];
    }
    __syncthreads();
    int warp = threadIdx.x >> 5, lane = threadIdx.x & 31;
    int node = blockIdx.x * 8 + warp;
    if (node >= n) return;
    int c = lane * 2;
    const float2* pacc = (const float2*)(g_acc2 + (size_t)node * 128);
    float2 l = pacc[lane];        // low, cols c..c+1
    float2 h = pacc[32 + lane];   // high
    l.x = fmaxf(l.x, 0.f); l.y = fmaxf(l.y, 0.f);
    h.x = fmaxf(h.x, 0.f); h.y = fmaxf(h.y, 0.f);
    __half2 r0 = __floats2half2_rn(l.x, h.x);
    __half2 r1 = __floats2half2_rn(l.y, h.y);
    float2 pk;
    ((__half2*)&pk)[0] = r0; ((__half2*)&pk)[1] = r1;
    ((float2*)(g_rel + (size_t)node * 64))[lane] = pk;

    float2 m2 = ((const float2*)(g_mlp + (size_t)node * 64))[lane];
    float dv[7];
#pragma unroll
    for (int k = 0; k < 3; k++) {
        dv[2 * k]     = l.x * sAl[k][c] + l.y * sAl[k][c + 1];
        dv[2 * k + 1] = h.x * sAh[k][c] + h.y * sAh[k][c + 1];
    }
    dv[6] = m2.x * sAm[c] + m2.y * sAm[c + 1];
#pragma unroll
    for (int off = 16; off; off >>= 1)
#pragma unroll
        for (int j = 0; j < 7; j++)
            dv[j] += __shfl_xor_sync(0xffffffffu, dv[j], off);
    if (lane == 0) {
        float* pt = g_t + (size_t)node * 8;
        pt[0] = dv[0]; pt[1] = dv[1];   // k=0 (homo)
        pt[2] = dv[2]; pt[3] = dv[3];   // k=1 (hete)
        pt[4] = dv[4]; pt[5] = dv[5];   // k=2 (unk)
        g_pd[(size_t)node * 8 + 6] = dv[6];
    }
}

// pass2: scatter per-edge logit contributions (one red2 per edge) + pack src|k.
__global__ void pass2_kernel(const int* __restrict__ src,
                             const int* __restrict__ dst,
                             const int* __restrict__ lab,
                             int e) {
    int i = blockIdx.x * blockDim.x + threadIdx.x;
    if (i >= e) return;
    int s = src[i], d = dst[i];
    int sl = lab[s], dl = lab[d];
    int k = ((sl | dl) < 0) ? 2 : ((sl != dl) ? 1 : 0);
    g_ek[i] = s | (k << 20);
    float2 t = *(const float2*)(g_t + (size_t)s * 8 + 2 * k);
    // pd slot pairs by bucket: k=0 -> (2,3), k=1 -> (0,1), k=2 -> (4,5)
    int slot = (k == 1) ? 0 : ((k == 0) ? 2 : 4);
    red2(g_pd + (size_t)d * 8 + slot, t.x, t.y);
}

// nodeB: attention softmax -> per-bucket weights + out init with mlp term.
__global__ void nodeB_kernel(const float* __restrict__ a7, float* __restrict__ out, int n) {
    __shared__ float sA7[49];
    if (threadIdx.x < 49) sA7[threadIdx.x] = a7[threadIdx.x];
    __syncthreads();
    int warp = threadIdx.x >> 5, lane = threadIdx.x & 31;
    int node = blockIdx.x * 8 + warp;
    if (node >= n) return;
    const float* pd = g_pd + (size_t)node * 8;
    float f[7];
#pragma unroll
    for (int j = 0; j < 7; j++)
        f[j] = 1.f / (1.f + expf(-pd[j]));
    float lg[7];
    float m = -1e30f;
#pragma unroll
    for (int i = 0; i < 7; i++) {
        float s = 0.f;
#pragma unroll
        for (int j = 0; j < 7; j++) s += f[j] * sA7[j * 7 + i];
        lg[i] = s * (1.0f / 7.0f);
        m = fmaxf(m, lg[i]);
    }
    float sum = 0.f;
#pragma unroll
    for (int i = 0; i < 7; i++) { lg[i] = expf(lg[i] - m); sum += lg[i]; }
    float inv = 7.0f / sum;
#pragma unroll
    for (int i = 0; i < 7; i++) lg[i] *= inv;

    if (lane < 3) {
        int k = lane;
        float wlk = (k == 1) ? lg[0] : ((k == 0) ? lg[2] : lg[4]);
        float whk = (k == 1) ? lg[1] : ((k == 0) ? lg[3] : lg[5]);
        ((float2*)(g_w2 + (size_t)node * 8))[k] = make_float2(wlk, whk);
    }
    float2 m2 = ((const float2*)(g_mlp + (size_t)node * 64))[lane];
    float2 r;
    r.x = lg[6] * m2.x;
    r.y = lg[6] * m2.y;
    ((float2*)(out + (size_t)node * 64))[lane] = r;
}

// pass3: weighted gather-scatter of relu'd packed features into out. 16 thr/edge.
__global__ void pass3_kernel(const int* __restrict__ dst, float* __restrict__ out, int e) {
    int tid = blockIdx.x * blockDim.x + threadIdx.x;
    int eid = tid >> 4;
    if (eid >= e) return;
    int c4 = tid & 15;
    int ek = g_ek[eid];
    int s = ek & 0xFFFFF;
    int k = ek >> 20;
    int d = dst[eid];
    float2 w = *(const float2*)(g_w2 + (size_t)d * 8 + 2 * k);
    float4 raw = ((const float4*)(g_rel + (size_t)s * 64))[c4];
    float2 f0 = __half22float2(*(__half2*)&raw.x);
    float2 f1 = __half22float2(*(__half2*)&raw.y);
    float2 f2 = __half22float2(*(__half2*)&raw.z);
    float2 f3 = __half22float2(*(__half2*)&raw.w);
    red4(out + (size_t)d * 64 + c4 * 4,
         w.x * f0.x + w.y * f0.y,
         w.x * f1.x + w.y * f1.y,
         w.x * f2.x + w.y * f2.y,
         w.x * f3.x + w.y * f3.y);
}

extern "C" void kernel_launch(void* const* d_in, const int* in_sizes, int n_in,
                              void* d_out, int out_size) {
    const float* x   = (const float*)d_in[0];
    const float* vl  = (const float*)d_in[1];
    const float* vh  = (const float*)d_in[2];
    const float* wl  = (const float*)d_in[3];
    const float* wh  = (const float*)d_in[4];
    const float* wm  = (const float*)d_in[5];
    const float* alf = (const float*)d_in[6];
    const float* ahf = (const float*)d_in[7];
    const float* alb = (const float*)d_in[8];
    const float* ahb = (const float*)d_in[9];
    const float* alu = (const float*)d_in[10];
    const float* ahu = (const float*)d_in[11];
    const float* am  = (const float*)d_in[12];
    const float* a7  = (const float*)d_in[13];
    const int* src   = (const int*)d_in[14];
    const int* dst   = (const int*)d_in[15];
    const int* lab   = (const int*)d_in[16];
    int n = in_sizes[0] / D;
    int e = in_sizes[14];
    float* out = (float*)d_out;

    int nz = n * 34;  // float4s: acc2 (32/node) + pd (2/node)
    zero_kernel<<<(nz + 255) / 256, 256>>>(n);
    gemm3_kernel<<<(n + 7) / 8, 256>>>(x, wl, wh, wm, n);
    int et = e * 16;
    spmm_kernel<<<(et + 255) / 256, 256>>>(vl, vh, src, dst, e);
    nodeA_kernel<<<(n + 7) / 8, 256>>>(alf, ahf, alb, ahb, alu, ahu, am, n);
    pass2_kernel<<<(e + 255) / 256, 256>>>(src, dst, lab, e);
    nodeB_kernel<<<(n + 7) / 8, 256>>>(a7, out, n);
    pass3_kernel<<<(et + 255) / 256, 256>>>(dst, out, e);
}

// round 5
// speedup vs baseline: 1.2107x; 1.0077x over previous
#include <cuda_runtime.h>
#include <cuda_fp16.h>
#include <math.h>

#define D 64
#define NMAX 100000
#define EMAX 1600000

// Scratch (__device__ globals, allocation-free rule)
__device__ __half2 g_xwp[(size_t)NMAX * 64];      // (xw_low[c], xw_high[c]) per col
__device__ float   g_mlp[(size_t)NMAX * 64];      // relu(x@W_mlp)
__device__ float   g_acc2[(size_t)NMAX * 128];    // [node][low 0:64 | high 64:128] fp32
__device__ __half2 g_rel[(size_t)NMAX * 64];      // relu'd acc packed (low, high)
__device__ __half2 g_B[3ULL * NMAX * 64];         // bucket sums, packed (low, high)
__device__ int     g_ek[EMAX];                    // src | (k<<20)

__device__ __forceinline__ void red4(float* a, float x, float y, float z, float w) {
    asm volatile("red.global.add.v4.f32 [%0], {%1, %2, %3, %4};"
                 :: "l"(a), "f"(x), "f"(y), "f"(z), "f"(w) : "memory");
}
__device__ __forceinline__ void redh8(__half2* a, unsigned x, unsigned y, unsigned z, unsigned w) {
    asm volatile("red.global.add.noftz.v4.f16x2 [%0], {%1, %2, %3, %4};"
                 :: "l"(a), "r"(x), "r"(y), "r"(z), "r"(w) : "memory");
}

__global__ void zero_kernel(int n) {
    int i = blockIdx.x * blockDim.x + threadIdx.x;
    int nacc = n * 32;                 // float4s in g_acc2
    int nb = n * 16;                   // float4s per bucket slab
    if (i < nacc) {
        ((float4*)g_acc2)[i] = make_float4(0.f, 0.f, 0.f, 0.f);
    } else {
        int j = i - nacc;
        int bucket = j / nb;
        if (bucket < 3) {
            int r = j - bucket * nb;
            ((float4*)(g_B + (size_t)bucket * NMAX * 64))[r] = make_float4(0.f, 0.f, 0.f, 0.f);
        }
    }
}

// 3 fused GEMMs: warp per row, weights staged in shared. Low/high packed to half2.
__global__ void gemm3_kernel(const float* __restrict__ x,
                             const float* __restrict__ wl,
                             const float* __restrict__ wh,
                             const float* __restrict__ wm,
                             int n) {
    __shared__ float sW[3][D][D];
    for (int i = threadIdx.x; i < D * D; i += blockDim.x) {
        sW[0][i >> 6][i & 63] = wl[i];
        sW[1][i >> 6][i & 63] = wh[i];
        sW[2][i >> 6][i & 63] = wm[i];
    }
    __syncthreads();
    int warp = threadIdx.x >> 5, lane = threadIdx.x & 31;
    int row = blockIdx.x * 8 + warp;
    if (row >= n) return;
    float2 xv = *(const float2*)(x + (size_t)row * D + lane * 2);
    float a0 = 0.f, a1 = 0.f, b0 = 0.f, b1 = 0.f, c0 = 0.f, c1 = 0.f;
#pragma unroll
    for (int k = 0; k < D; k++) {
        float xk = __shfl_sync(0xffffffffu, (k & 1) ? xv.y : xv.x, k >> 1);
        a0 += xk * sW[0][k][lane];      a1 += xk * sW[0][k][lane + 32];
        b0 += xk * sW[1][k][lane];      b1 += xk * sW[1][k][lane + 32];
        c0 += xk * sW[2][k][lane];      c1 += xk * sW[2][k][lane + 32];
    }
    size_t o = (size_t)row * 64;
    g_xwp[o + lane]      = __floats2half2_rn(a0, b0);
    g_xwp[o + lane + 32] = __floats2half2_rn(a1, b1);
    g_mlp[o + lane] = fmaxf(c0, 0.f);
    g_mlp[o + lane + 32] = fmaxf(c1, 0.f);
}

// pass1: edge-parallel SpMM, 16 threads/edge; lane 0 also classifies the edge bucket.
__global__ void spmm_kernel(const float* __restrict__ vl,
                            const float* __restrict__ vh,
                            const int* __restrict__ src,
                            const int* __restrict__ dst,
                            const int* __restrict__ lab,
                            int e) {
    int tid = blockIdx.x * blockDim.x + threadIdx.x;
    int eid = tid >> 4;
    if (eid >= e) return;
    int c4 = tid & 15;
    int s = src[eid], d = dst[eid];
    if (c4 == 0) {
        int sl = lab[s], dl = lab[d];
        int k = ((sl | dl) < 0) ? 2 : ((sl != dl) ? 1 : 0);
        g_ek[eid] = s | (k << 20);
    }
    float a = vl[eid], b = vh[eid];
    float4 raw = ((const float4*)(g_xwp + (size_t)s * 64))[c4];
    float2 f0 = __half22float2(*(__half2*)&raw.x);
    float2 f1 = __half22float2(*(__half2*)&raw.y);
    float2 f2 = __half22float2(*(__half2*)&raw.z);
    float2 f3 = __half22float2(*(__half2*)&raw.w);
    float* pd = g_acc2 + (size_t)d * 128 + c4 * 4;
    red4(pd,      a * f0.x, a * f1.x, a * f2.x, a * f3.x);
    red4(pd + 64, b * f0.y, b * f1.y, b * f2.y, b * f3.y);
}

// nodeA: elementwise relu(acc) -> packed half2 g_rel. 16 threads/node.
__global__ void nodeA_kernel(int n) {
    int i = blockIdx.x * blockDim.x + threadIdx.x;
    if (i >= n * 16) return;
    int node = i >> 4, c4 = i & 15;
    const float4* pl = (const float4*)(g_acc2 + (size_t)node * 128);
    float4 lo = pl[c4];
    float4 hi = pl[16 + c4];
    __half2 h0 = __floats2half2_rn(fmaxf(lo.x, 0.f), fmaxf(hi.x, 0.f));
    __half2 h1 = __floats2half2_rn(fmaxf(lo.y, 0.f), fmaxf(hi.y, 0.f));
    __half2 h2 = __floats2half2_rn(fmaxf(lo.z, 0.f), fmaxf(hi.z, 0.f));
    __half2 h3 = __floats2half2_rn(fmaxf(lo.w, 0.f), fmaxf(hi.w, 0.f));
    float4 pk;
    ((__half2*)&pk)[0] = h0; ((__half2*)&pk)[1] = h1;
    ((__half2*)&pk)[2] = h2; ((__half2*)&pk)[3] = h3;
    ((float4*)(g_rel + (size_t)node * 64))[c4] = pk;
}

// pass2': bucketed feature aggregation with fp16 vector atomics. 16 threads/edge.
__global__ void pass2_kernel(const int* __restrict__ dst, int e) {
    int tid = blockIdx.x * blockDim.x + threadIdx.x;
    int eid = tid >> 4;
    if (eid >= e) return;
    int c4 = tid & 15;
    int ek = g_ek[eid];
    int s = ek & 0xFFFFF;
    int k = ek >> 20;
    int d = dst[eid];
    float4 raw = ((const float4*)(g_rel + (size_t)s * 64))[c4];
    __half2* p = g_B + (size_t)k * NMAX * 64 + (size_t)d * 64 + c4 * 4;
    redh8(p, __float_as_uint(raw.x), __float_as_uint(raw.y),
             __float_as_uint(raw.z), __float_as_uint(raw.w));
}

// nodeB': streamed epilogue — logits from bucket dots, softmax, combine. Warp/node.
__global__ void nodeB_kernel(const float* __restrict__ alf, const float* __restrict__ ahf,
                             const float* __restrict__ alb, const float* __restrict__ ahb,
                             const float* __restrict__ alu, const float* __restrict__ ahu,
                             const float* __restrict__ am,  const float* __restrict__ a7,
                             float* __restrict__ out, int n) {
    __shared__ float sV[7][D];   // slot order: alf,ahf,alb,ahb,alu,ahu,am
    __shared__ float sA7[49];
    if (threadIdx.x < D) {
        int c = threadIdx.x;
        sV[0][c] = alf[c]; sV[1][c] = ahf[c]; sV[2][c] = alb[c];
        sV[3][c] = ahb[c]; sV[4][c] = alu[c]; sV[5][c] = ahu[c];
        sV[6][c] = am[c];
    }
    if (threadIdx.x < 49) sA7[threadIdx.x] = a7[threadIdx.x];
    __syncthreads();
    int warp = threadIdx.x >> 5, lane = threadIdx.x & 31;
    int node = blockIdx.x * 8 + warp;
    if (node >= n) return;
    int c = lane * 2;
    size_t o = (size_t)node * 64;
    // bucket pairs for cols c, c+1: each float2 holds 2 half2 = (low,high) per col
    float2 homo2 = ((const float2*)(g_B + 0ULL * NMAX * 64 + o))[lane];
    float2 hete2 = ((const float2*)(g_B + 1ULL * NMAX * 64 + o))[lane];
    float2 unk2  = ((const float2*)(g_B + 2ULL * NMAX * 64 + o))[lane];
    float2 m2    = ((const float2*)(g_mlp + o))[lane];
    float2 hoA = __half22float2(((__half2*)&homo2)[0]);  // x=low[c], y=high[c]
    float2 hoB = __half22float2(((__half2*)&homo2)[1]);  // col c+1
    float2 heA = __half22float2(((__half2*)&hete2)[0]);
    float2 heB = __half22float2(((__half2*)&hete2)[1]);
    float2 unA = __half22float2(((__half2*)&unk2)[0]);
    float2 unB = __half22float2(((__half2*)&unk2)[1]);

    float ps[7];
    ps[0] = heA.x * sV[0][c] + heB.x * sV[0][c + 1];
    ps[1] = heA.y * sV[1][c] + heB.y * sV[1][c + 1];
    ps[2] = hoA.x * sV[2][c] + hoB.x * sV[2][c + 1];
    ps[3] = hoA.y * sV[3][c] + hoB.y * sV[3][c + 1];
    ps[4] = unA.x * sV[4][c] + unB.x * sV[4][c + 1];
    ps[5] = unA.y * sV[5][c] + unB.y * sV[5][c + 1];
    ps[6] = m2.x  * sV[6][c] + m2.y  * sV[6][c + 1];
#pragma unroll
    for (int off = 16; off; off >>= 1)
#pragma unroll
        for (int j = 0; j < 7; j++)
            ps[j] += __shfl_xor_sync(0xffffffffu, ps[j], off);

    float f[7];
#pragma unroll
    for (int j = 0; j < 7; j++)
        f[j] = 1.f / (1.f + __expf(-ps[j]));
    float lg[7];
    float m = -1e30f;
#pragma unroll
    for (int i = 0; i < 7; i++) {
        float s = 0.f;
#pragma unroll
        for (int j = 0; j < 7; j++) s += f[j] * sA7[j * 7 + i];
        lg[i] = s * (1.0f / 7.0f);
        m = fmaxf(m, lg[i]);
    }
    float sum = 0.f;
#pragma unroll
    for (int i = 0; i < 7; i++) { lg[i] = __expf(lg[i] - m); sum += lg[i]; }
    float inv = 7.0f / sum;
#pragma unroll
    for (int i = 0; i < 7; i++) lg[i] *= inv;

    float2 r;
    r.x = lg[0] * heA.x + lg[1] * heA.y + lg[2] * hoA.x + lg[3] * hoA.y
        + lg[4] * unA.x + lg[5] * unA.y + lg[6] * m2.x;
    r.y = lg[0] * heB.x + lg[1] * heB.y + lg[2] * hoB.x + lg[3] * hoB.y
        + lg[4] * unB.x + lg[5] * unB.y + lg[6] * m2.y;
    *(float2*)(out + o + c) = r;
}

extern "C" void kernel_launch(void* const* d_in, const int* in_sizes, int n_in,
                              void* d_out, int out_size) {
    const float* x   = (const float*)d_in[0];
    const float* vl  = (const float*)d_in[1];
    const float* vh  = (const float*)d_in[2];
    const float* wl  = (const float*)d_in[3];
    const float* wh  = (const float*)d_in[4];
    const float* wm  = (const float*)d_in[5];
    const float* alf = (const float*)d_in[6];
    const float* ahf = (const float*)d_in[7];
    const float* alb = (const float*)d_in[8];
    const float* ahb = (const float*)d_in[9];
    const float* alu = (const float*)d_in[10];
    const float* ahu = (const float*)d_in[11];
    const float* am  = (const float*)d_in[12];
    const float* a7  = (const float*)d_in[13];
    const int* src   = (const int*)d_in[14];
    const int* dst   = (const int*)d_in[15];
    const int* lab   = (const int*)d_in[16];
    int n = in_sizes[0] / D;
    int e = in_sizes[14];
    float* out = (float*)d_out;

    int nz = n * 80;  // float4s: acc2 (32/node) + 3 bucket slabs (16/node each)
    zero_kernel<<<(nz + 255) / 256, 256>>>(n);
    gemm3_kernel<<<(n + 7) / 8, 256>>>(x, wl, wh, wm, n);
    int et = e * 16;
    spmm_kernel<<<(et + 255) / 256, 256>>>(vl, vh, src, dst, lab, e);
    int nt = n * 16;
    nodeA_kernel<<<(nt + 255) / 256, 256>>>(n);
    pass2_kernel<<<(et + 255) / 256, 256>>>(dst, e);
    nodeB_kernel<<<(n + 7) / 8, 256>>>(alf, ahf, alb, ahb, alu, ahu, am, a7, out, n);
}

// round 6
// speedup vs baseline: 1.3341x; 1.1019x over previous
#include <cuda_runtime.h>
#include <cuda_fp16.h>
#include <math.h>

#define D 64
#define NMAX 100000
#define EMAX 1600000

// Scratch (__device__ globals, allocation-free rule)
__device__ __half2 g_xwp[(size_t)NMAX * 64];   // (xw_low[c], xw_high[c]) per col
__device__ float   g_mlp[(size_t)NMAX * 64];   // relu(x@W_mlp)
__device__ __half2 g_acc[(size_t)NMAX * 64];   // SpMM accum, packed (low, high), fp16 atomics
__device__ __half2 g_B[3ULL * NMAX * 64];      // bucket sums, packed (low, high)
__device__ int     g_ek[EMAX];                 // src | (k<<20)

__device__ __forceinline__ void redh8(__half2* a, unsigned x, unsigned y, unsigned z, unsigned w) {
    asm volatile("red.global.add.noftz.v4.f16x2 [%0], {%1, %2, %3, %4};"
                 :: "l"(a), "r"(x), "r"(y), "r"(z), "r"(w) : "memory");
}

__global__ void zero_kernel(int n) {
    int i = blockIdx.x * blockDim.x + threadIdx.x;
    int nacc = n * 16;                 // float4s in g_acc
    if (i < nacc) {
        ((float4*)g_acc)[i] = make_float4(0.f, 0.f, 0.f, 0.f);
    } else {
        int j = i - nacc;
        if (j < n * 48)
            ((float4*)g_B)[j] = make_float4(0.f, 0.f, 0.f, 0.f);
    }
}

// 3 fused GEMMs: warp per row, weights staged in shared. Low/high packed to half2.
__global__ void gemm3_kernel(const float* __restrict__ x,
                             const float* __restrict__ wl,
                             const float* __restrict__ wh,
                             const float* __restrict__ wm,
                             int n) {
    __shared__ float sW[3][D][D];
    for (int i = threadIdx.x; i < D * D; i += blockDim.x) {
        sW[0][i >> 6][i & 63] = wl[i];
        sW[1][i >> 6][i & 63] = wh[i];
        sW[2][i >> 6][i & 63] = wm[i];
    }
    __syncthreads();
    int warp = threadIdx.x >> 5, lane = threadIdx.x & 31;
    int row = blockIdx.x * 8 + warp;
    if (row >= n) return;
    float2 xv = *(const float2*)(x + (size_t)row * D + lane * 2);
    float a0 = 0.f, a1 = 0.f, b0 = 0.f, b1 = 0.f, c0 = 0.f, c1 = 0.f;
#pragma unroll
    for (int k = 0; k < D; k++) {
        float xk = __shfl_sync(0xffffffffu, (k & 1) ? xv.y : xv.x, k >> 1);
        a0 += xk * sW[0][k][lane];      a1 += xk * sW[0][k][lane + 32];
        b0 += xk * sW[1][k][lane];      b1 += xk * sW[1][k][lane + 32];
        c0 += xk * sW[2][k][lane];      c1 += xk * sW[2][k][lane + 32];
    }
    size_t o = (size_t)row * 64;
    g_xwp[o + lane]      = __floats2half2_rn(a0, b0);
    g_xwp[o + lane + 32] = __floats2half2_rn(a1, b1);
    g_mlp[o + lane] = fmaxf(c0, 0.f);
    g_mlp[o + lane + 32] = fmaxf(c1, 0.f);
}

// pass1: edge-parallel SpMM. 16 threads/edge; ONE fp16x8 vector-red per thread.
__global__ void spmm_kernel(const float* __restrict__ vl,
                            const float* __restrict__ vh,
                            const int* __restrict__ src,
                            const int* __restrict__ dst,
                            const int* __restrict__ lab,
                            int e) {
    int tid = blockIdx.x * blockDim.x + threadIdx.x;
    int eid = tid >> 4;
    if (eid >= e) return;
    int c4 = tid & 15;
    int s = src[eid], d = dst[eid];
    if (c4 == 0) {
        int sl = lab[s], dl = lab[d];
        int k = ((sl | dl) < 0) ? 2 : ((sl != dl) ? 1 : 0);
        g_ek[eid] = s | (k << 20);
    }
    __half2 cf = __floats2half2_rn(vl[eid], vh[eid]);
    float4 raw = ((const float4*)(g_xwp + (size_t)s * 64))[c4];
    __half2 p0 = __hmul2(*(__half2*)&raw.x, cf);
    __half2 p1 = __hmul2(*(__half2*)&raw.y, cf);
    __half2 p2 = __hmul2(*(__half2*)&raw.z, cf);
    __half2 p3 = __hmul2(*(__half2*)&raw.w, cf);
    redh8(g_acc + (size_t)d * 64 + c4 * 4,
          *(unsigned*)&p0, *(unsigned*)&p1, *(unsigned*)&p2, *(unsigned*)&p3);
}

// pass2: bucketed aggregation; relu applied on the gather. 16 threads/edge.
__global__ void pass2_kernel(const int* __restrict__ dst, int e) {
    int tid = blockIdx.x * blockDim.x + threadIdx.x;
    int eid = tid >> 4;
    if (eid >= e) return;
    int c4 = tid & 15;
    int ek = g_ek[eid];
    int s = ek & 0xFFFFF;
    int k = ek >> 20;
    int d = dst[eid];
    float4 raw = ((const float4*)(g_acc + (size_t)s * 64))[c4];
    __half2 z = __float2half2_rn(0.f);
    __half2 p0 = __hmax2(*(__half2*)&raw.x, z);
    __half2 p1 = __hmax2(*(__half2*)&raw.y, z);
    __half2 p2 = __hmax2(*(__half2*)&raw.z, z);
    __half2 p3 = __hmax2(*(__half2*)&raw.w, z);
    redh8(g_B + (size_t)k * NMAX * 64 + (size_t)d * 64 + c4 * 4,
          *(unsigned*)&p0, *(unsigned*)&p1, *(unsigned*)&p2, *(unsigned*)&p3);
}

// nodeB: streamed epilogue — logits from bucket dots, softmax, combine. Warp/node.
__global__ void nodeB_kernel(const float* __restrict__ alf, const float* __restrict__ ahf,
                             const float* __restrict__ alb, const float* __restrict__ ahb,
                             const float* __restrict__ alu, const float* __restrict__ ahu,
                             const float* __restrict__ am,  const float* __restrict__ a7,
                             float* __restrict__ out, int n) {
    __shared__ float sV[7][D];   // slot order: alf,ahf,alb,ahb,alu,ahu,am
    __shared__ float sA7[49];
    if (threadIdx.x < D) {
        int c = threadIdx.x;
        sV[0][c] = alf[c]; sV[1][c] = ahf[c]; sV[2][c] = alb[c];
        sV[3][c] = ahb[c]; sV[4][c] = alu[c]; sV[5][c] = ahu[c];
        sV[6][c] = am[c];
    }
    if (threadIdx.x < 49) sA7[threadIdx.x] = a7[threadIdx.x];
    __syncthreads();
    int warp = threadIdx.x >> 5, lane = threadIdx.x & 31;
    int node = blockIdx.x * 8 + warp;
    if (node >= n) return;
    int c = lane * 2;
    size_t o = (size_t)node * 64;
    float2 homo2 = ((const float2*)(g_B + 0ULL * NMAX * 64 + o))[lane];
    float2 hete2 = ((const float2*)(g_B + 1ULL * NMAX * 64 + o))[lane];
    float2 unk2  = ((const float2*)(g_B + 2ULL * NMAX * 64 + o))[lane];
    float2 m2    = ((const float2*)(g_mlp + o))[lane];
    float2 hoA = __half22float2(((__half2*)&homo2)[0]);  // x=low[c], y=high[c]
    float2 hoB = __half22float2(((__half2*)&homo2)[1]);  // col c+1
    float2 heA = __half22float2(((__half2*)&hete2)[0]);
    float2 heB = __half22float2(((__half2*)&hete2)[1]);
    float2 unA = __half22float2(((__half2*)&unk2)[0]);
    float2 unB = __half22float2(((__half2*)&unk2)[1]);

    float ps[7];
    ps[0] = heA.x * sV[0][c] + heB.x * sV[0][c + 1];
    ps[1] = heA.y * sV[1][c] + heB.y * sV[1][c + 1];
    ps[2] = hoA.x * sV[2][c] + hoB.x * sV[2][c + 1];
    ps[3] = hoA.y * sV[3][c] + hoB.y * sV[3][c + 1];
    ps[4] = unA.x * sV[4][c] + unB.x * sV[4][c + 1];
    ps[5] = unA.y * sV[5][c] + unB.y * sV[5][c + 1];
    ps[6] = m2.x  * sV[6][c] + m2.y  * sV[6][c + 1];
#pragma unroll
    for (int off = 16; off; off >>= 1)
#pragma unroll
        for (int j = 0; j < 7; j++)
            ps[j] += __shfl_xor_sync(0xffffffffu, ps[j], off);

    float f[7];
#pragma unroll
    for (int j = 0; j < 7; j++)
        f[j] = 1.f / (1.f + __expf(-ps[j]));
    float lg[7];
    float m = -1e30f;
#pragma unroll
    for (int i = 0; i < 7; i++) {
        float s = 0.f;
#pragma unroll
        for (int j = 0; j < 7; j++) s += f[j] * sA7[j * 7 + i];
        lg[i] = s * (1.0f / 7.0f);
        m = fmaxf(m, lg[i]);
    }
    float sum = 0.f;
#pragma unroll
    for (int i = 0; i < 7; i++) { lg[i] = __expf(lg[i] - m); sum += lg[i]; }
    float inv = 7.0f / sum;
#pragma unroll
    for (int i = 0; i < 7; i++) lg[i] *= inv;

    float2 r;
    r.x = lg[0] * heA.x + lg[1] * heA.y + lg[2] * hoA.x + lg[3] * hoA.y
        + lg[4] * unA.x + lg[5] * unA.y + lg[6] * m2.x;
    r.y = lg[0] * heB.x + lg[1] * heB.y + lg[2] * hoB.x + lg[3] * hoB.y
        + lg[4] * unB.x + lg[5] * unB.y + lg[6] * m2.y;
    *(float2*)(out + o + c) = r;
}

extern "C" void kernel_launch(void* const* d_in, const int* in_sizes, int n_in,
                              void* d_out, int out_size) {
    const float* x   = (const float*)d_in[0];
    const float* vl  = (const float*)d_in[1];
    const float* vh  = (const float*)d_in[2];
    const float* wl  = (const float*)d_in[3];
    const float* wh  = (const float*)d_in[4];
    const float* wm  = (const float*)d_in[5];
    const float* alf = (const float*)d_in[6];
    const float* ahf = (const float*)d_in[7];
    const float* alb = (const float*)d_in[8];
    const float* ahb = (const float*)d_in[9];
    const float* alu = (const float*)d_in[10];
    const float* ahu = (const float*)d_in[11];
    const float* am  = (const float*)d_in[12];
    const float* a7  = (const float*)d_in[13];
    const int* src   = (const int*)d_in[14];
    const int* dst   = (const int*)d_in[15];
    const int* lab   = (const int*)d_in[16];
    int n = in_sizes[0] / D;
    int e = in_sizes[14];
    float* out = (float*)d_out;

    int nz = n * 64;  // float4s: acc (16/node) + 3 bucket slabs (16/node each)
    zero_kernel<<<(nz + 255) / 256, 256>>>(n);
    gemm3_kernel<<<(n + 7) / 8, 256>>>(x, wl, wh, wm, n);
    int et = e * 16;
    spmm_kernel<<<(et + 255) / 256, 256>>>(vl, vh, src, dst, lab, e);
    pass2_kernel<<<(et + 255) / 256, 256>>>(dst, e);
    nodeB_kernel<<<(n + 7) / 8, 256>>>(alf, ahf, alb, ahb, alu, ahu, am, a7, out, n);
}